// round 2
// baseline (speedup 1.0000x reference)
#include <cuda_runtime.h>
#include <cstdint>

// Problem constants
#define BATCH 4096
#define TT    120
#define II    64
#define HH    128
#define G3    384   // 3*H

typedef unsigned long long u64;

// 755MB fp32 scratch for precomputed input gates, layout [T][B][3H]
__device__ float g_xg[(size_t)TT * BATCH * G3];

// ---------------- packed f32x2 helpers (sm_103a FFMA2) ----------------
__device__ __forceinline__ u64 ffma2(u64 a, u64 b, u64 c) {
    u64 d;
    asm("fma.rn.f32x2 %0, %1, %2, %3;" : "=l"(d) : "l"(a), "l"(b), "l"(c));
    return d;
}
__device__ __forceinline__ u64 pack2(float x, float y) {
    u64 d;
    asm("mov.b64 %0, {%1, %2};" : "=l"(d) : "f"(x), "f"(y));
    return d;
}
__device__ __forceinline__ void unpack2(u64 a, float& x, float& y) {
    asm("mov.b64 {%0, %1}, %2;" : "=f"(x), "=f"(y) : "l"(a));
}

__device__ __forceinline__ float sigf(float v) {
    return __fdividef(1.0f, 1.0f + __expf(-v));
}
__device__ __forceinline__ float tanhf_fast(float v) {
    // tanh(v) = 2*sigma(2v) - 1 ; saturates correctly at +-inf
    return __fdividef(2.0f, 1.0f + __expf(-2.0f * v)) - 1.0f;
}

// =====================================================================
// Kernel 1: x_gates[t][b][g] = x[b][t][:] @ W_ih[g][:] + b_ih[g]
// SMEM: WtI[64][385] transposed+padded, bias[384], xT[64][34]
// 512 threads: j = tid&127 (gate unit), mg = tid>>7 (8-row group)
// =====================================================================
#define XP_WPAD 385
#define XP_SMEM_FLOATS (II * XP_WPAD + G3 + II * 34)
#define NTILES (TT * (BATCH / 32))   // 15360

__global__ void __launch_bounds__(512)
xproj_kernel(const float* __restrict__ x,
             const float* __restrict__ Wih,
             const float* __restrict__ bih)
{
    extern __shared__ float sm[];
    float* Wt   = sm;                    // [64][385]
    float* bias = Wt + II * XP_WPAD;     // [384]
    float* xT   = bias + G3;             // [64][34]

    const int tid = threadIdx.x;

    // Load W_ih transposed: Wt[k][n] = W_ih[n][k]. Coalesced global read.
    for (int i = tid; i < G3 * II; i += 512) {
        int n = i >> 6;       // 0..383
        int k = i & 63;       // 0..63
        Wt[k * XP_WPAD + n] = Wih[i];
    }
    for (int i = tid; i < G3; i += 512) bias[i] = bih[i];
    __syncthreads();

    const int j     = tid & 127;
    const int mg    = tid >> 7;
    const int mbase = mg * 8;
    const float br = bias[j], bz = bias[128 + j], bn = bias[256 + j];

    for (int tile = blockIdx.x; tile < NTILES; tile += gridDim.x) {
        const int t  = tile % TT;
        const int b0 = (tile / TT) << 5;

        // load x tile transposed: xT[k][m] = x[b0+m][t][k]
        for (int i = tid; i < 32 * II; i += 512) {
            int m = i >> 6;
            int k = i & 63;
            xT[k * 34 + m] = x[((size_t)(b0 + m) * TT + t) * II + k];
        }
        __syncthreads();

        u64 ar[4], az[4], an[4];
#pragma unroll
        for (int p = 0; p < 4; ++p) { ar[p] = 0ull; az[p] = 0ull; an[p] = 0ull; }

#pragma unroll 4
        for (int k = 0; k < II; ++k) {
            const float* wrow = Wt + k * XP_WPAD;
            float wr = wrow[j], wz = wrow[128 + j], wn = wrow[256 + j];
            u64 wr2 = pack2(wr, wr), wz2 = pack2(wz, wz), wn2 = pack2(wn, wn);
            const u64* hp = reinterpret_cast<const u64*>(xT + k * 34 + mbase);
#pragma unroll
            for (int p = 0; p < 4; ++p) {
                u64 h2 = hp[p];
                ar[p] = ffma2(h2, wr2, ar[p]);
                az[p] = ffma2(h2, wz2, az[p]);
                an[p] = ffma2(h2, wn2, an[p]);
            }
        }

        // write out: g_xg[t][b][g]
#pragma unroll
        for (int p = 0; p < 4; ++p) {
            float r0, r1, z0, z1, n0, n1;
            unpack2(ar[p], r0, r1);
            unpack2(az[p], z0, z1);
            unpack2(an[p], n0, n1);
#pragma unroll
            for (int e = 0; e < 2; ++e) {
                int mm = 2 * p + e;
                float vr = e ? r1 : r0;
                float vz = e ? z1 : z0;
                float vn = e ? n1 : n0;
                float* g = &g_xg[((size_t)t * BATCH + b0 + mbase + mm) * G3];
                g[j]       = vr + br;
                g[128 + j] = vz + bz;
                g[256 + j] = vn + bn;
            }
        }
        __syncthreads();   // protect xT before next tile's load
    }
}

// =====================================================================
// Kernel 2: fused GRU recurrence. 128 CTAs x 32 batch rows each.
// SMEM: Wt[128][385] (W_hh transposed+padded), bias[384], hT[128][34]
// Thread (j = tid&127, mg = tid>>7) owns gate columns {j, j+128, j+256}
// for 8 rows m = mg*8 .. mg*8+7 (4 f32x2 pairs).
// =====================================================================
#define R_WPAD 385
#define R_SMEM_FLOATS (HH * R_WPAD + G3 + HH * 34)

__global__ void __launch_bounds__(512)
gru_rec_kernel(const float* __restrict__ Whh,
               const float* __restrict__ bhh,
               float* __restrict__ out,
               int write_hT)
{
    extern __shared__ float sm[];
    float* Wt   = sm;                    // [128][385]
    float* bias = Wt + HH * R_WPAD;      // [384]
    float* hT   = bias + G3;             // [128][34], hT[k][m]

    const int tid = threadIdx.x;

    // Wt[k][n] = W_hh[n][k]; coalesced global read, conflict-free smem write (pad 385)
    for (int i = tid; i < G3 * HH; i += 512) {
        int n = i >> 7;       // 0..383
        int k = i & 127;      // 0..127
        Wt[k * R_WPAD + n] = Whh[i];
    }
    for (int i = tid; i < G3; i += 512) bias[i] = bhh[i];
    for (int i = tid; i < HH * 34; i += 512) hT[i] = 0.0f;
    __syncthreads();

    const int j     = tid & 127;
    const int mg    = tid >> 7;
    const int mbase = mg * 8;
    const int b0    = blockIdx.x << 5;
    const float br = bias[j], bz = bias[128 + j], bn = bias[256 + j];

    float hnew[8];

    for (int t = 0; t < TT; ++t) {
        // Prefetch input gates early (independent of h) to hide DRAM latency
        float xr[8], xz[8], xn[8];
#pragma unroll
        for (int mm = 0; mm < 8; ++mm) {
            const float* g = &g_xg[((size_t)t * BATCH + b0 + mbase + mm) * G3];
            xr[mm] = g[j];
            xz[mm] = g[128 + j];
            xn[mm] = g[256 + j];
        }

        u64 ar[4], az[4], an[4];
#pragma unroll
        for (int p = 0; p < 4; ++p) { ar[p] = 0ull; az[p] = 0ull; an[p] = 0ull; }

#pragma unroll 4
        for (int k = 0; k < HH; ++k) {
            const float* wrow = Wt + k * R_WPAD;
            float wr = wrow[j], wz = wrow[128 + j], wn = wrow[256 + j];
            u64 wr2 = pack2(wr, wr), wz2 = pack2(wz, wz), wn2 = pack2(wn, wn);
            const u64* hp = reinterpret_cast<const u64*>(hT + k * 34 + mbase);
#pragma unroll
            for (int p = 0; p < 4; ++p) {
                u64 h2 = hp[p];   // broadcast across warp (same addr all lanes)
                ar[p] = ffma2(h2, wr2, ar[p]);
                az[p] = ffma2(h2, wz2, az[p]);
                an[p] = ffma2(h2, wn2, an[p]);
            }
        }

        // Gate math + output write (reads of hT complete before the barrier)
#pragma unroll
        for (int p = 0; p < 4; ++p) {
            float r0, r1, z0, z1, n0, n1;
            unpack2(ar[p], r0, r1);
            unpack2(az[p], z0, z1);
            unpack2(an[p], n0, n1);
#pragma unroll
            for (int e = 0; e < 2; ++e) {
                int mm = 2 * p + e;
                float hrv = e ? r1 : r0;
                float hzv = e ? z1 : z0;
                float hnv = e ? n1 : n0;
                float r  = sigf(xr[mm] + hrv + br);
                float z  = sigf(xz[mm] + hzv + bz);
                float nn = tanhf_fast(xn[mm] + r * (hnv + bn));
                float ho = hT[j * 34 + mbase + mm];
                float hv = nn + z * (ho - nn);
                hnew[mm] = hv;
                out[((size_t)(b0 + mbase + mm) * TT + t) * HH + j] = hv;
            }
        }
        __syncthreads();            // all reads of old h done
#pragma unroll
        for (int mm = 0; mm < 8; ++mm)
            hT[j * 34 + mbase + mm] = hnew[mm];
        __syncthreads();            // new h visible before next step
    }

    if (write_hT) {
        float* outF = out + (size_t)BATCH * TT * HH;
#pragma unroll
        for (int mm = 0; mm < 8; ++mm)
            outF[(size_t)(b0 + mbase + mm) * HH + j] = hnew[mm];
    }
}

// =====================================================================
extern "C" void kernel_launch(void* const* d_in, const int* in_sizes, int n_in,
                              void* d_out, int out_size)
{
    const float* x   = (const float*)d_in[0];
    const float* Wih = (const float*)d_in[1];
    const float* Whh = (const float*)d_in[2];
    const float* bih = (const float*)d_in[3];
    const float* bhh = (const float*)d_in[4];
    float* out = (float*)d_out;
    (void)in_sizes; (void)n_in;

    const int xp_smem = XP_SMEM_FLOATS * sizeof(float);   // ~108.8 KB
    const int r_smem  = R_SMEM_FLOATS  * sizeof(float);   // ~216.1 KB

    cudaFuncSetAttribute(xproj_kernel,
                         cudaFuncAttributeMaxDynamicSharedMemorySize, xp_smem);
    cudaFuncSetAttribute(gru_rec_kernel,
                         cudaFuncAttributeMaxDynamicSharedMemorySize, r_smem);

    int write_hT = (out_size >= BATCH * TT * HH + BATCH * HH) ? 1 : 0;

    xproj_kernel<<<1280, 512, xp_smem>>>(x, Wih, bih);
    gru_rec_kernel<<<BATCH / 32, 512, r_smem>>>(Whh, bhh, out, write_hT);
}